// round 1
// baseline (speedup 1.0000x reference)
#include <cuda_runtime.h>
#include <cuda_bf16.h>
#include <math.h>
#include <stdint.h>

// ---------------- problem constants ----------------
#define BB   4
#define SVL  1024
#define SEX  64
#define SS   1088          // SVL + SEX
#define DVL  2048
#define DEX  1024
#define HQ   16
#define HKV  8
#define DH   128
#define IVL  6144
#define IEX  3072
#define MVL  (BB*SVL)      // 4096
#define MEX  (BB*SEX)      // 256
#define EPSV 1e-6f
#define ATT_SCALE 0.08838834764831845f   // 128^-0.5
#define LOG2_THETA 22.253496664211536f   // log2(5e6)

// ---------------- device scratch (no allocs allowed) ----------------
__device__ float g_X1[MVL*DVL];
__device__ float g_X2[MEX*DEX];
__device__ float g_Qr1[(size_t)MVL*(HQ*DH)];
__device__ float g_Kr1[(size_t)MVL*(HKV*DH)];
__device__ float g_Vr1[(size_t)MVL*(HKV*DH)];
__device__ float g_Qr2[(size_t)MEX*(HQ*DH)];
__device__ float g_Kr2[(size_t)MEX*(HKV*DH)];
__device__ float g_Vr2[(size_t)MEX*(HKV*DH)];
__device__ float g_Q[(size_t)BB*HQ*SS*DH];
__device__ float g_K[(size_t)BB*HKV*SS*DH];
__device__ float g_V[(size_t)BB*HKV*SS*DH];
__device__ float g_A1[(size_t)MVL*(HQ*DH)];
__device__ float g_A2[(size_t)MEX*(HQ*DH)];
__device__ float g_O1[(size_t)MVL*DVL];
__device__ float g_O2[(size_t)MEX*DEX];
__device__ float g_G1[(size_t)MVL*IVL];
__device__ float g_G2[(size_t)MEX*IEX];

// ---------------- rmsnorm over rows ----------------
__global__ __launch_bounds__(256) void rmsnorm_k(const float* __restrict__ x,
                                                 const float* __restrict__ w,
                                                 float* __restrict__ y, int D)
{
    const int row = blockIdx.x;
    const float* xr = x + (size_t)row * D;
    float s = 0.f;
    for (int i = threadIdx.x; i < D; i += 256) { float v = xr[i]; s += v * v; }
    #pragma unroll
    for (int o = 16; o; o >>= 1) s += __shfl_xor_sync(0xffffffffu, s, o);
    __shared__ float ws[8];
    if ((threadIdx.x & 31) == 0) ws[threadIdx.x >> 5] = s;
    __syncthreads();
    float tot = 0.f;
    #pragma unroll
    for (int i = 0; i < 8; i++) tot += ws[i];
    const float r = rsqrtf(tot / (float)D + EPSV);
    float* yr = y + (size_t)row * D;
    for (int i = threadIdx.x; i < D; i += 256) yr[i] = xr[i] * r * w[i];
}

// ---------------- head rmsnorm + RoPE + scatter to [B,H,S,DH] ----------------
__global__ __launch_bounds__(128) void qkv_post_k(const float* __restrict__ raw,
                                                  const float* __restrict__ w,
                                                  const int* __restrict__ pos_ids,
                                                  float* __restrict__ out,
                                                  int H, int sCount, int seqOff,
                                                  int doNorm, int doRope)
{
    __shared__ float sh[DH];
    __shared__ float ws[4];
    const int d = threadIdx.x;
    const int s = blockIdx.x, h = blockIdx.y, b = blockIdx.z;
    const int row = b * sCount + s;
    float v = raw[((size_t)row * H + h) * DH + d];
    if (doNorm) {
        float v2 = v * v;
        #pragma unroll
        for (int o = 16; o; o >>= 1) v2 += __shfl_xor_sync(0xffffffffu, v2, o);
        if ((d & 31) == 0) ws[d >> 5] = v2;
        __syncthreads();
        float tot = ws[0] + ws[1] + ws[2] + ws[3];
        v = v * rsqrtf(tot * (1.0f / DH) + EPSV) * w[d];
    }
    const int gs = seqOff + s;
    if (doRope) {
        sh[d] = v;
        __syncthreads();
        const float partner = (d < 64) ? -sh[d + 64] : sh[d - 64];
        const int pos = pos_ids[b * SS + gs];
        const float fr = (float)(d & 63) * (1.0f / 64.0f);
        const float invf = exp2f(-fr * LOG2_THETA);
        const float ang = (float)pos * invf;
        float sn, cs;
        sincosf(ang, &sn, &cs);
        v = v * cs + partner * sn;
    }
    out[(((size_t)b * H + h) * SS + gs) * DH + d] = v;
}

// ---------------- SGEMM: C = A[M,K] @ B[K,N] (+R) ; GATED: silu(A@B0)*(A@B1) ----------------
template<int GATED>
__global__ __launch_bounds__(256) void sgemm_k(const float* __restrict__ A,
                                               const float* __restrict__ B0,
                                               const float* __restrict__ B1,
                                               const float* __restrict__ R,
                                               float* __restrict__ C,
                                               int M, int N, int K)
{
    __shared__ float As[16][68];
    __shared__ float Bs0[16][64];
    __shared__ float Bs1[GATED ? 16 : 1][64];
    const int tid = threadIdx.x;
    const int tx = tid & 15, ty = tid >> 4;
    const int bm = blockIdx.y * 64, bn = blockIdx.x * 64;
    const int ar = tid >> 2, ac = (tid & 3) << 2;
    const int br = tid >> 4, bc = (tid & 15) << 2;
    float acc0[4][4] = {};
    float acc1[4][4] = {};
    const float* Ap  = A  + (size_t)(bm + ar) * K + ac;
    const float* B0p = B0 + (size_t)br * N + bn + bc;
    const float* B1p = GATED ? (B1 + (size_t)br * N + bn + bc) : B0;
    for (int kt = 0; kt < K; kt += 16) {
        float4 a4 = *(const float4*)(Ap + kt);
        As[ac + 0][ar] = a4.x; As[ac + 1][ar] = a4.y;
        As[ac + 2][ar] = a4.z; As[ac + 3][ar] = a4.w;
        *(float4*)&Bs0[br][bc] = *(const float4*)(B0p + (size_t)kt * N);
        if (GATED) *(float4*)&Bs1[br][bc] = *(const float4*)(B1p + (size_t)kt * N);
        __syncthreads();
        #pragma unroll
        for (int k = 0; k < 16; k++) {
            float4 av = *(const float4*)&As[k][ty << 2];
            float4 bv = *(const float4*)&Bs0[k][tx << 2];
            float am[4] = {av.x, av.y, av.z, av.w};
            float bn_[4] = {bv.x, bv.y, bv.z, bv.w};
            #pragma unroll
            for (int m = 0; m < 4; m++)
                #pragma unroll
                for (int n = 0; n < 4; n++)
                    acc0[m][n] += am[m] * bn_[n];
            if (GATED) {
                float4 bw = *(const float4*)&Bs1[k][tx << 2];
                float bu[4] = {bw.x, bw.y, bw.z, bw.w};
                #pragma unroll
                for (int m = 0; m < 4; m++)
                    #pragma unroll
                    for (int n = 0; n < 4; n++)
                        acc1[m][n] += am[m] * bu[n];
            }
        }
        __syncthreads();
    }
    #pragma unroll
    for (int m = 0; m < 4; m++) {
        const size_t row = bm + (ty << 2) + m;
        const size_t col = bn + (tx << 2);
        float vals[4];
        #pragma unroll
        for (int n = 0; n < 4; n++) {
            if (GATED) {
                float g = acc0[m][n];
                vals[n] = g / (1.f + __expf(-g)) * acc1[m][n];
            } else {
                vals[n] = acc0[m][n];
            }
        }
        if (R) {
            float4 r4 = *(const float4*)(R + row * N + col);
            vals[0] += r4.x; vals[1] += r4.y; vals[2] += r4.z; vals[3] += r4.w;
        }
        *(float4*)(C + row * N + col) = make_float4(vals[0], vals[1], vals[2], vals[3]);
    }
}

// ---------------- flash attention (fp32, online softmax) ----------------
// BQ=64 query rows per block, BK=32 keys per tile. 256 threads.
#define AQ 64
#define AK 32
#define QPAD 132   // DH + 4 : banks of rows differ by 4 -> no row-conflicts on Q
#define SPAD 33
#define ATTN_SMEM ((AQ*QPAD + AK*QPAD + AK*QPAD + AQ*SPAD + 3*AQ) * 4)

__global__ __launch_bounds__(256) void attn_k(const float* __restrict__ Q,
                                              const float* __restrict__ Kg,
                                              const float* __restrict__ Vg,
                                              const float* __restrict__ mask,
                                              float* __restrict__ att1,
                                              float* __restrict__ att2)
{
    extern __shared__ float sm[];
    float* Qs   = sm;                       // AQ * QPAD
    float* Ks   = Qs + AQ * QPAD;           // AK * QPAD
    float* Vs   = Ks + AK * QPAD;           // AK * QPAD
    float* Scr  = Vs + AK * QPAD;           // AQ * SPAD
    float* mrow = Scr + AQ * SPAD;          // AQ
    float* lrow = mrow + AQ;                // AQ
    float* crow = lrow + AQ;                // AQ

    const int tid = threadIdx.x;
    const int b = blockIdx.z, h = blockIdx.y;
    const int q0 = blockIdx.x * AQ;
    const int kvh = h >> 1;                 // GQA: repeat factor 2
    const float* Qb = Q  + ((size_t)(b * HQ  + h)   * SS + q0) * DH;
    const float* Kb = Kg + ((size_t)(b * HKV + kvh) * SS) * DH;
    const float* Vb = Vg + ((size_t)(b * HKV + kvh) * SS) * DH;

    for (int i = tid * 4; i < AQ * DH; i += 1024) {
        int r = i >> 7, c = i & 127;
        *(float4*)&Qs[r * QPAD + c] = *(const float4*)&Qb[i];
    }
    if (tid < AQ) { mrow[tid] = -1e30f; lrow[tid] = 0.f; }
    const int ty = tid >> 4, tx = tid & 15;
    float acc[4][8];
    #pragma unroll
    for (int m = 0; m < 4; m++)
        #pragma unroll
        for (int d = 0; d < 8; d++) acc[m][d] = 0.f;
    __syncthreads();

    for (int k0 = 0; k0 < SS; k0 += AK) {
        for (int i = tid * 4; i < AK * DH; i += 1024) {
            int r = i >> 7, c = i & 127;
            *(float4*)&Ks[r * QPAD + c] = *(const float4*)&Kb[(size_t)k0 * DH + i];
            *(float4*)&Vs[r * QPAD + c] = *(const float4*)&Vb[(size_t)k0 * DH + i];
        }
        __syncthreads();

        // scores: rows ty*4..+3, cols tx*2..+1
        float sacc[4][2] = {};
        #pragma unroll 8
        for (int kk = 0; kk < DH; kk += 4) {
            float4 kv0 = *(const float4*)&Ks[(tx * 2 + 0) * QPAD + kk];
            float4 kv1 = *(const float4*)&Ks[(tx * 2 + 1) * QPAD + kk];
            #pragma unroll
            for (int m = 0; m < 4; m++) {
                float4 qv = *(const float4*)&Qs[(ty * 4 + m) * QPAD + kk];
                sacc[m][0] += qv.x*kv0.x + qv.y*kv0.y + qv.z*kv0.z + qv.w*kv0.w;
                sacc[m][1] += qv.x*kv1.x + qv.y*kv1.y + qv.z*kv1.z + qv.w*kv1.w;
            }
        }
        #pragma unroll
        for (int m = 0; m < 4; m++)
            #pragma unroll
            for (int n = 0; n < 2; n++) {
                const int qr = q0 + ty * 4 + m;
                const int kc = k0 + tx * 2 + n;
                float v = sacc[m][n] * ATT_SCALE + mask[((size_t)b * SS + qr) * SS + kc];
                Scr[(ty * 4 + m) * SPAD + (tx * 2 + n)] = v;
            }
        __syncthreads();

        // online softmax row update (one thread per row)
        if (tid < AQ) {
            float mo = mrow[tid], mx = mo;
            #pragma unroll 8
            for (int c = 0; c < AK; c++) mx = fmaxf(mx, Scr[tid * SPAD + c]);
            float corr = __expf(mo - mx);
            float l = lrow[tid] * corr, ps = 0.f;
            #pragma unroll 8
            for (int c = 0; c < AK; c++) {
                float p = __expf(Scr[tid * SPAD + c] - mx);
                Scr[tid * SPAD + c] = p;
                ps += p;
            }
            mrow[tid] = mx; lrow[tid] = l + ps; crow[tid] = corr;
        }
        __syncthreads();

        // acc = acc*corr + P @ V
        float cr[4];
        #pragma unroll
        for (int m = 0; m < 4; m++) cr[m] = crow[ty * 4 + m];
        #pragma unroll
        for (int m = 0; m < 4; m++)
            #pragma unroll
            for (int d = 0; d < 8; d++) acc[m][d] *= cr[m];
        #pragma unroll 4
        for (int c = 0; c < AK; c++) {
            float4 v0 = *(const float4*)&Vs[c * QPAD + tx * 8];
            float4 v1 = *(const float4*)&Vs[c * QPAD + tx * 8 + 4];
            #pragma unroll
            for (int m = 0; m < 4; m++) {
                float p = Scr[(ty * 4 + m) * SPAD + c];
                acc[m][0] += p * v0.x; acc[m][1] += p * v0.y;
                acc[m][2] += p * v0.z; acc[m][3] += p * v0.w;
                acc[m][4] += p * v1.x; acc[m][5] += p * v1.y;
                acc[m][6] += p * v1.z; acc[m][7] += p * v1.w;
            }
        }
        __syncthreads();
    }

    #pragma unroll
    for (int m = 0; m < 4; m++) {
        const int qr = q0 + ty * 4 + m;
        const float li = 1.f / lrow[ty * 4 + m];
        float* op;
        if (qr < SVL) op = att1 + ((size_t)(b * SVL + qr)) * (HQ * DH) + h * DH + tx * 8;
        else          op = att2 + ((size_t)(b * SEX + (qr - SVL))) * (HQ * DH) + h * DH + tx * 8;
        *(float4*)op       = make_float4(acc[m][0]*li, acc[m][1]*li, acc[m][2]*li, acc[m][3]*li);
        *(float4*)(op + 4) = make_float4(acc[m][4]*li, acc[m][5]*li, acc[m][6]*li, acc[m][7]*li);
    }
}

// ---------------- launch ----------------
static inline void launch_gemm(const float* A, const float* Bm, float* Cm,
                               int M, int N, int K, const float* R = nullptr)
{
    sgemm_k<0><<<dim3(N / 64, M / 64), 256>>>(A, Bm, nullptr, R, Cm, M, N, K);
}

extern "C" void kernel_launch(void* const* d_in, const int* in_sizes, int n_in,
                              void* d_out, int out_size)
{
    (void)in_sizes; (void)n_in; (void)out_size;
    const float* hs_vl  = (const float*)d_in[0];
    const float* hs_ex  = (const float*)d_in[1];
    const int*   posids = (const int*)  d_in[2];
    const float* mask   = (const float*)d_in[3];
    const float* vl_ln1 = (const float*)d_in[4];
    const float* vl_wq  = (const float*)d_in[5];
    const float* vl_wk  = (const float*)d_in[6];
    const float* vl_wv  = (const float*)d_in[7];
    const float* vl_qn  = (const float*)d_in[8];
    const float* vl_kn  = (const float*)d_in[9];
    const float* vl_wo  = (const float*)d_in[10];
    const float* vl_ln2 = (const float*)d_in[11];
    const float* vl_wg  = (const float*)d_in[12];
    const float* vl_wu  = (const float*)d_in[13];
    const float* vl_wd  = (const float*)d_in[14];
    const float* ex_ln1 = (const float*)d_in[15];
    const float* ex_wq  = (const float*)d_in[16];
    const float* ex_wk  = (const float*)d_in[17];
    const float* ex_wv  = (const float*)d_in[18];
    const float* ex_qn  = (const float*)d_in[19];
    const float* ex_kn  = (const float*)d_in[20];
    const float* ex_wo  = (const float*)d_in[21];
    const float* ex_ln2 = (const float*)d_in[22];
    const float* ex_wg  = (const float*)d_in[23];
    const float* ex_wu  = (const float*)d_in[24];
    const float* ex_wd  = (const float*)d_in[25];

    float* out_vl = (float*)d_out;
    float* out_ex = out_vl + (size_t)MVL * DVL;

    float *X1,*X2,*Qr1,*Kr1,*Vr1,*Qr2,*Kr2,*Vr2,*Qc,*Kc,*Vc,*A1,*A2,*O1,*O2,*G1,*G2;
    cudaGetSymbolAddress((void**)&X1,  g_X1);
    cudaGetSymbolAddress((void**)&X2,  g_X2);
    cudaGetSymbolAddress((void**)&Qr1, g_Qr1);
    cudaGetSymbolAddress((void**)&Kr1, g_Kr1);
    cudaGetSymbolAddress((void**)&Vr1, g_Vr1);
    cudaGetSymbolAddress((void**)&Qr2, g_Qr2);
    cudaGetSymbolAddress((void**)&Kr2, g_Kr2);
    cudaGetSymbolAddress((void**)&Vr2, g_Vr2);
    cudaGetSymbolAddress((void**)&Qc,  g_Q);
    cudaGetSymbolAddress((void**)&Kc,  g_K);
    cudaGetSymbolAddress((void**)&Vc,  g_V);
    cudaGetSymbolAddress((void**)&A1,  g_A1);
    cudaGetSymbolAddress((void**)&A2,  g_A2);
    cudaGetSymbolAddress((void**)&O1,  g_O1);
    cudaGetSymbolAddress((void**)&O2,  g_O2);
    cudaGetSymbolAddress((void**)&G1,  g_G1);
    cudaGetSymbolAddress((void**)&G2,  g_G2);

    // 1) input rmsnorm
    rmsnorm_k<<<MVL, 256>>>(hs_vl, vl_ln1, X1, DVL);
    rmsnorm_k<<<MEX, 256>>>(hs_ex, ex_ln1, X2, DEX);

    // 2) QKV projections
    launch_gemm(X1, vl_wq, Qr1, MVL, HQ * DH,  DVL);
    launch_gemm(X1, vl_wk, Kr1, MVL, HKV * DH, DVL);
    launch_gemm(X1, vl_wv, Vr1, MVL, HKV * DH, DVL);
    launch_gemm(X2, ex_wq, Qr2, MEX, HQ * DH,  DEX);
    launch_gemm(X2, ex_wk, Kr2, MEX, HKV * DH, DEX);
    launch_gemm(X2, ex_wv, Vr2, MEX, HKV * DH, DEX);

    // 3) head rmsnorm + RoPE + scatter to [B,H,S,DH]
    qkv_post_k<<<dim3(SVL, HQ,  BB), 128>>>(Qr1, vl_qn, posids, Qc, HQ,  SVL, 0,   1, 1);
    qkv_post_k<<<dim3(SEX, HQ,  BB), 128>>>(Qr2, ex_qn, posids, Qc, HQ,  SEX, SVL, 1, 1);
    qkv_post_k<<<dim3(SVL, HKV, BB), 128>>>(Kr1, vl_kn, posids, Kc, HKV, SVL, 0,   1, 1);
    qkv_post_k<<<dim3(SEX, HKV, BB), 128>>>(Kr2, ex_kn, posids, Kc, HKV, SEX, SVL, 1, 1);
    qkv_post_k<<<dim3(SVL, HKV, BB), 128>>>(Vr1, nullptr, posids, Vc, HKV, SVL, 0,   0, 0);
    qkv_post_k<<<dim3(SEX, HKV, BB), 128>>>(Vr2, nullptr, posids, Vc, HKV, SEX, SVL, 0, 0);

    // 4) attention (flash, online softmax, mask applied additively)
    cudaFuncSetAttribute(attn_k, cudaFuncAttributeMaxDynamicSharedMemorySize, ATTN_SMEM);
    attn_k<<<dim3(SS / AQ, HQ, BB), 256, ATTN_SMEM>>>(Qc, Kc, Vc, mask, A1, A2);

    // 5) output projection + residual
    launch_gemm(A1, vl_wo, O1, MVL, DVL, HQ * DH, hs_vl);
    launch_gemm(A2, ex_wo, O2, MEX, DEX, HQ * DH, hs_ex);

    // 6) pre-MLP rmsnorm
    rmsnorm_k<<<MVL, 256>>>(O1, vl_ln2, X1, DVL);
    rmsnorm_k<<<MEX, 256>>>(O2, ex_ln2, X2, DEX);

    // 7) gated MLP up: silu(x@wg) * (x@wu)
    sgemm_k<1><<<dim3(IVL / 64, MVL / 64), 256>>>(X1, vl_wg, vl_wu, nullptr, G1, MVL, IVL, DVL);
    sgemm_k<1><<<dim3(IEX / 64, MEX / 64), 256>>>(X2, ex_wg, ex_wu, nullptr, G2, MEX, IEX, DEX);

    // 8) down projection + residual -> outputs
    launch_gemm(G1, vl_wd, out_vl, MVL, DVL, IVL, O1);
    launch_gemm(G2, ex_wd, out_ex, MEX, DEX, IEX, O2);
}

// round 3
// speedup vs baseline: 1.0975x; 1.0975x over previous
#include <cuda_runtime.h>
#include <cuda_bf16.h>
#include <math.h>
#include <stdint.h>

// ---------------- problem constants ----------------
#define BB   4
#define SVL  1024
#define SEX  64
#define SS   1088          // SVL + SEX
#define DVL  2048
#define DEX  1024
#define HQ   16
#define HKV  8
#define DH   128
#define IVL  6144
#define IEX  3072
#define MVL  (BB*SVL)      // 4096
#define MEX  (BB*SEX)      // 256
#define EPSV 1e-6f
#define ATT_SCALE 0.08838834764831845f   // 128^-0.5
#define LOG2_THETA 22.253496664211536f   // log2(5e6)

// ---------------- device scratch (no allocs allowed) ----------------
__device__ float g_X1[MVL*DVL];
__device__ float g_X2[MEX*DEX];
__device__ float g_Qr1[(size_t)MVL*(HQ*DH)];
__device__ float g_Kr1[(size_t)MVL*(HKV*DH)];
__device__ float g_Vr1[(size_t)MVL*(HKV*DH)];
__device__ float g_Qr2[(size_t)MEX*(HQ*DH)];
__device__ float g_Kr2[(size_t)MEX*(HKV*DH)];
__device__ float g_Vr2[(size_t)MEX*(HKV*DH)];
__device__ float g_Q[(size_t)BB*HQ*SS*DH];
__device__ float g_K[(size_t)BB*HKV*SS*DH];
__device__ float g_V[(size_t)BB*HKV*SS*DH];
__device__ float g_A1[(size_t)MVL*(HQ*DH)];
__device__ float g_A2[(size_t)MEX*(HQ*DH)];
__device__ float g_O1[(size_t)MVL*DVL];
__device__ float g_O2[(size_t)MEX*DEX];
__device__ float g_G1[(size_t)MVL*IVL];
__device__ float g_G2[(size_t)MEX*IEX];
__device__ float g_U1[(size_t)MVL*IVL];
__device__ float g_U2[(size_t)MEX*IEX];

// ---------------- rmsnorm over rows ----------------
__global__ __launch_bounds__(256) void rmsnorm_k(const float* __restrict__ x,
                                                 const float* __restrict__ w,
                                                 float* __restrict__ y, int D)
{
    const int row = blockIdx.x;
    const float* xr = x + (size_t)row * D;
    float s = 0.f;
    for (int i = threadIdx.x; i < D; i += 256) { float v = xr[i]; s += v * v; }
    #pragma unroll
    for (int o = 16; o; o >>= 1) s += __shfl_xor_sync(0xffffffffu, s, o);
    __shared__ float ws[8];
    if ((threadIdx.x & 31) == 0) ws[threadIdx.x >> 5] = s;
    __syncthreads();
    float tot = 0.f;
    #pragma unroll
    for (int i = 0; i < 8; i++) tot += ws[i];
    const float r = rsqrtf(tot / (float)D + EPSV);
    float* yr = y + (size_t)row * D;
    for (int i = threadIdx.x; i < D; i += 256) yr[i] = xr[i] * r * w[i];
}

// ---------------- head rmsnorm + RoPE + scatter to [B,H,S,DH] ----------------
__global__ __launch_bounds__(128) void qkv_post_k(const float* __restrict__ raw,
                                                  const float* __restrict__ w,
                                                  const int* __restrict__ pos_ids,
                                                  float* __restrict__ out,
                                                  int H, int sCount, int seqOff,
                                                  int doNorm, int doRope)
{
    __shared__ float sh[DH];
    __shared__ float ws[4];
    const int d = threadIdx.x;
    const int s = blockIdx.x, h = blockIdx.y, b = blockIdx.z;
    const int row = b * sCount + s;
    float v = raw[((size_t)row * H + h) * DH + d];
    if (doNorm) {
        float v2 = v * v;
        #pragma unroll
        for (int o = 16; o; o >>= 1) v2 += __shfl_xor_sync(0xffffffffu, v2, o);
        if ((d & 31) == 0) ws[d >> 5] = v2;
        __syncthreads();
        float tot = ws[0] + ws[1] + ws[2] + ws[3];
        v = v * rsqrtf(tot * (1.0f / DH) + EPSV) * w[d];
    }
    const int gs = seqOff + s;
    if (doRope) {
        sh[d] = v;
        __syncthreads();
        const float partner = (d < 64) ? -sh[d + 64] : sh[d - 64];
        const int pos = pos_ids[b * SS + gs];
        const float fr = (float)(d & 63) * (1.0f / 64.0f);
        const float invf = exp2f(-fr * LOG2_THETA);
        const float ang = (float)pos * invf;
        float sn, cs;
        sincosf(ang, &sn, &cs);
        v = v * cs + partner * sn;
    }
    out[(((size_t)b * H + h) * SS + gs) * DH + d] = v;
}

// ---------------- SGEMM 128x128x16, 256 thr, 8x8/thread, double-buffered ----------------
// C = A[M,K] @ B[K,N] (+R). M % 128 == 0, N % 128 == 0, K % 16 == 0.
__global__ __launch_bounds__(256) void sgemm128_k(const float* __restrict__ A,
                                                  const float* __restrict__ B,
                                                  const float* __restrict__ R,
                                                  float* __restrict__ C,
                                                  int M, int N, int K)
{
    __shared__ float As[2][16][132];   // [buf][k][m], padded
    __shared__ float Bs[2][16][128];   // [buf][k][n]
    const int tid = threadIdx.x;
    const int tx = tid & 15, ty = tid >> 4;
    const int bm = blockIdx.y * 128, bn = blockIdx.x * 128;

    // A tile loader: 128 rows x 16 cols, 2 float4/thread
    const int ar = tid >> 2;            // 0..63
    const int ac = (tid & 3) << 2;      // 0,4,8,12
    // B tile loader: 16 rows x 128 cols, 2 float4/thread
    const int br = tid >> 5;            // 0..7
    const int bc = (tid & 31) << 2;     // 0..124

    const float* Ap = A + (size_t)(bm + ar) * K + ac;
    const float* Bp = B + (size_t)br * N + bn + bc;

    float acc[8][8];
    #pragma unroll
    for (int i = 0; i < 8; i++)
        #pragma unroll
        for (int j = 0; j < 8; j++) acc[i][j] = 0.f;

    const int TILES = K >> 4;
    float4 ra0, ra1, rb0, rb1;

    // preload tile 0
    ra0 = *(const float4*)(Ap);
    ra1 = *(const float4*)(Ap + (size_t)64 * K);
    rb0 = *(const float4*)(Bp);
    rb1 = *(const float4*)(Bp + (size_t)8 * N);

#define STORE_TILE(bufi)                                                     \
    do {                                                                     \
        As[bufi][ac + 0][ar] = ra0.x; As[bufi][ac + 1][ar] = ra0.y;          \
        As[bufi][ac + 2][ar] = ra0.z; As[bufi][ac + 3][ar] = ra0.w;          \
        As[bufi][ac + 0][ar + 64] = ra1.x; As[bufi][ac + 1][ar + 64] = ra1.y;\
        As[bufi][ac + 2][ar + 64] = ra1.z; As[bufi][ac + 3][ar + 64] = ra1.w;\
        *(float4*)&Bs[bufi][br][bc]     = rb0;                               \
        *(float4*)&Bs[bufi][br + 8][bc] = rb1;                               \
    } while (0)

    STORE_TILE(0);
    __syncthreads();

    int buf = 0;
    for (int kt = 0; kt < TILES; kt++) {
        if (kt + 1 < TILES) {
            const int ko = (kt + 1) << 4;
            ra0 = *(const float4*)(Ap + ko);
            ra1 = *(const float4*)(Ap + (size_t)64 * K + ko);
            rb0 = *(const float4*)(Bp + (size_t)ko * N);
            rb1 = *(const float4*)(Bp + (size_t)(ko + 8) * N);
        }
        #pragma unroll
        for (int k = 0; k < 16; k++) {
            float4 a0v = *(const float4*)&As[buf][k][ty << 2];
            float4 a1v = *(const float4*)&As[buf][k][64 + (ty << 2)];
            float4 b0v = *(const float4*)&Bs[buf][k][tx << 2];
            float4 b1v = *(const float4*)&Bs[buf][k][64 + (tx << 2)];
            float am[8] = {a0v.x, a0v.y, a0v.z, a0v.w, a1v.x, a1v.y, a1v.z, a1v.w};
            float bv[8] = {b0v.x, b0v.y, b0v.z, b0v.w, b1v.x, b1v.y, b1v.z, b1v.w};
            #pragma unroll
            for (int i = 0; i < 8; i++)
                #pragma unroll
                for (int j = 0; j < 8; j++)
                    acc[i][j] += am[i] * bv[j];
        }
        if (kt + 1 < TILES) {
            STORE_TILE(buf ^ 1);
            __syncthreads();
            buf ^= 1;
        }
    }
#undef STORE_TILE

    // epilogue: 8 rows x (2 x float4) per thread
    #pragma unroll
    for (int i = 0; i < 8; i++) {
        const int rloc = (i < 4) ? ((ty << 2) + i) : (64 + (ty << 2) + i - 4);
        const size_t row = (size_t)(bm + rloc);
        #pragma unroll
        for (int jb = 0; jb < 2; jb++) {
            const size_t col = (size_t)(bn + jb * 64 + (tx << 2));
            float4 v = make_float4(acc[i][jb*4+0], acc[i][jb*4+1],
                                   acc[i][jb*4+2], acc[i][jb*4+3]);
            if (R) {
                float4 r4 = *(const float4*)(R + row * N + col);
                v.x += r4.x; v.y += r4.y; v.z += r4.z; v.w += r4.w;
            }
            *(float4*)(C + row * N + col) = v;
        }
    }
}

// ---------------- elementwise: g = silu(g) * u ----------------
__global__ __launch_bounds__(256) void silu_mul_k(float* __restrict__ g,
                                                  const float* __restrict__ u,
                                                  size_t n4)
{
    size_t i = (size_t)blockIdx.x * 256 + threadIdx.x;
    if (i >= n4) return;
    float4 gv = ((const float4*)g)[i];
    float4 uv = ((const float4*)u)[i];
    gv.x = gv.x / (1.f + __expf(-gv.x)) * uv.x;
    gv.y = gv.y / (1.f + __expf(-gv.y)) * uv.y;
    gv.z = gv.z / (1.f + __expf(-gv.z)) * uv.z;
    gv.w = gv.w / (1.f + __expf(-gv.w)) * uv.w;
    ((float4*)g)[i] = gv;
}

// ---------------- flash attention (fp32, online softmax) ----------------
#define AQ 64
#define AK 32
#define QPAD 132
#define SPAD 33
#define ATTN_SMEM ((AQ*QPAD + AK*QPAD + AK*QPAD + AQ*SPAD + 3*AQ) * 4)

__global__ __launch_bounds__(256) void attn_k(const float* __restrict__ Q,
                                              const float* __restrict__ Kg,
                                              const float* __restrict__ Vg,
                                              const float* __restrict__ mask,
                                              float* __restrict__ att1,
                                              float* __restrict__ att2)
{
    extern __shared__ float sm[];
    float* Qs   = sm;
    float* Ks   = Qs + AQ * QPAD;
    float* Vs   = Ks + AK * QPAD;
    float* Scr  = Vs + AK * QPAD;
    float* mrow = Scr + AQ * SPAD;
    float* lrow = mrow + AQ;
    float* crow = lrow + AQ;

    const int tid = threadIdx.x;
    const int b = blockIdx.z, h = blockIdx.y;
    const int q0 = blockIdx.x * AQ;
    const int kvh = h >> 1;
    const float* Qb = Q  + ((size_t)(b * HQ  + h)   * SS + q0) * DH;
    const float* Kb = Kg + ((size_t)(b * HKV + kvh) * SS) * DH;
    const float* Vb = Vg + ((size_t)(b * HKV + kvh) * SS) * DH;

    for (int i = tid * 4; i < AQ * DH; i += 1024) {
        int r = i >> 7, c = i & 127;
        *(float4*)&Qs[r * QPAD + c] = *(const float4*)&Qb[i];
    }
    if (tid < AQ) { mrow[tid] = -1e30f; lrow[tid] = 0.f; }
    const int ty = tid >> 4, tx = tid & 15;
    float acc[4][8];
    #pragma unroll
    for (int m = 0; m < 4; m++)
        #pragma unroll
        for (int d = 0; d < 8; d++) acc[m][d] = 0.f;
    __syncthreads();

    for (int k0 = 0; k0 < SS; k0 += AK) {
        for (int i = tid * 4; i < AK * DH; i += 1024) {
            int r = i >> 7, c = i & 127;
            *(float4*)&Ks[r * QPAD + c] = *(const float4*)&Kb[(size_t)k0 * DH + i];
            *(float4*)&Vs[r * QPAD + c] = *(const float4*)&Vb[(size_t)k0 * DH + i];
        }
        __syncthreads();

        float sacc[4][2] = {};
        #pragma unroll 8
        for (int kk = 0; kk < DH; kk += 4) {
            float4 kv0 = *(const float4*)&Ks[(tx * 2 + 0) * QPAD + kk];
            float4 kv1 = *(const float4*)&Ks[(tx * 2 + 1) * QPAD + kk];
            #pragma unroll
            for (int m = 0; m < 4; m++) {
                float4 qv = *(const float4*)&Qs[(ty * 4 + m) * QPAD + kk];
                sacc[m][0] += qv.x*kv0.x + qv.y*kv0.y + qv.z*kv0.z + qv.w*kv0.w;
                sacc[m][1] += qv.x*kv1.x + qv.y*kv1.y + qv.z*kv1.z + qv.w*kv1.w;
            }
        }
        #pragma unroll
        for (int m = 0; m < 4; m++)
            #pragma unroll
            for (int n = 0; n < 2; n++) {
                const int qr = q0 + ty * 4 + m;
                const int kc = k0 + tx * 2 + n;
                float v = sacc[m][n] * ATT_SCALE + mask[((size_t)b * SS + qr) * SS + kc];
                Scr[(ty * 4 + m) * SPAD + (tx * 2 + n)] = v;
            }
        __syncthreads();

        if (tid < AQ) {
            float mo = mrow[tid], mx = mo;
            #pragma unroll 8
            for (int c = 0; c < AK; c++) mx = fmaxf(mx, Scr[tid * SPAD + c]);
            float corr = __expf(mo - mx);
            float l = lrow[tid] * corr, ps = 0.f;
            #pragma unroll 8
            for (int c = 0; c < AK; c++) {
                float p = __expf(Scr[tid * SPAD + c] - mx);
                Scr[tid * SPAD + c] = p;
                ps += p;
            }
            mrow[tid] = mx; lrow[tid] = l + ps; crow[tid] = corr;
        }
        __syncthreads();

        float cr[4];
        #pragma unroll
        for (int m = 0; m < 4; m++) cr[m] = crow[ty * 4 + m];
        #pragma unroll
        for (int m = 0; m < 4; m++)
            #pragma unroll
            for (int d = 0; d < 8; d++) acc[m][d] *= cr[m];
        #pragma unroll 4
        for (int c = 0; c < AK; c++) {
            float4 v0 = *(const float4*)&Vs[c * QPAD + tx * 8];
            float4 v1 = *(const float4*)&Vs[c * QPAD + tx * 8 + 4];
            #pragma unroll
            for (int m = 0; m < 4; m++) {
                float p = Scr[(ty * 4 + m) * SPAD + c];
                acc[m][0] += p * v0.x; acc[m][1] += p * v0.y;
                acc[m][2] += p * v0.z; acc[m][3] += p * v0.w;
                acc[m][4] += p * v1.x; acc[m][5] += p * v1.y;
                acc[m][6] += p * v1.z; acc[m][7] += p * v1.w;
            }
        }
        __syncthreads();
    }

    #pragma unroll
    for (int m = 0; m < 4; m++) {
        const int qr = q0 + ty * 4 + m;
        const float li = 1.f / lrow[ty * 4 + m];
        float* op;
        if (qr < SVL) op = att1 + ((size_t)(b * SVL + qr)) * (HQ * DH) + h * DH + tx * 8;
        else          op = att2 + ((size_t)(b * SEX + (qr - SVL))) * (HQ * DH) + h * DH + tx * 8;
        *(float4*)op       = make_float4(acc[m][0]*li, acc[m][1]*li, acc[m][2]*li, acc[m][3]*li);
        *(float4*)(op + 4) = make_float4(acc[m][4]*li, acc[m][5]*li, acc[m][6]*li, acc[m][7]*li);
    }
}

// ---------------- launch ----------------
static inline void launch_gemm(const float* A, const float* Bm, float* Cm,
                               int M, int N, int K, const float* R = nullptr)
{
    sgemm128_k<<<dim3(N / 128, M / 128), 256>>>(A, Bm, R, Cm, M, N, K);
}

extern "C" void kernel_launch(void* const* d_in, const int* in_sizes, int n_in,
                              void* d_out, int out_size)
{
    (void)in_sizes; (void)n_in; (void)out_size;
    const float* hs_vl  = (const float*)d_in[0];
    const float* hs_ex  = (const float*)d_in[1];
    const int*   posids = (const int*)  d_in[2];
    const float* mask   = (const float*)d_in[3];
    const float* vl_ln1 = (const float*)d_in[4];
    const float* vl_wq  = (const float*)d_in[5];
    const float* vl_wk  = (const float*)d_in[6];
    const float* vl_wv  = (const float*)d_in[7];
    const float* vl_qn  = (const float*)d_in[8];
    const float* vl_kn  = (const float*)d_in[9];
    const float* vl_wo  = (const float*)d_in[10];
    const float* vl_ln2 = (const float*)d_in[11];
    const float* vl_wg  = (const float*)d_in[12];
    const float* vl_wu  = (const float*)d_in[13];
    const float* vl_wd  = (const float*)d_in[14];
    const float* ex_ln1 = (const float*)d_in[15];
    const float* ex_wq  = (const float*)d_in[16];
    const float* ex_wk  = (const float*)d_in[17];
    const float* ex_wv  = (const float*)d_in[18];
    const float* ex_qn  = (const float*)d_in[19];
    const float* ex_kn  = (const float*)d_in[20];
    const float* ex_wo  = (const float*)d_in[21];
    const float* ex_ln2 = (const float*)d_in[22];
    const float* ex_wg  = (const float*)d_in[23];
    const float* ex_wu  = (const float*)d_in[24];
    const float* ex_wd  = (const float*)d_in[25];

    float* out_vl = (float*)d_out;
    float* out_ex = out_vl + (size_t)MVL * DVL;

    float *X1,*X2,*Qr1,*Kr1,*Vr1,*Qr2,*Kr2,*Vr2,*Qc,*Kc,*Vc,*A1,*A2,*O1,*O2,*G1,*G2,*U1,*U2;
    cudaGetSymbolAddress((void**)&X1,  g_X1);
    cudaGetSymbolAddress((void**)&X2,  g_X2);
    cudaGetSymbolAddress((void**)&Qr1, g_Qr1);
    cudaGetSymbolAddress((void**)&Kr1, g_Kr1);
    cudaGetSymbolAddress((void**)&Vr1, g_Vr1);
    cudaGetSymbolAddress((void**)&Qr2, g_Qr2);
    cudaGetSymbolAddress((void**)&Kr2, g_Kr2);
    cudaGetSymbolAddress((void**)&Vr2, g_Vr2);
    cudaGetSymbolAddress((void**)&Qc,  g_Q);
    cudaGetSymbolAddress((void**)&Kc,  g_K);
    cudaGetSymbolAddress((void**)&Vc,  g_V);
    cudaGetSymbolAddress((void**)&A1,  g_A1);
    cudaGetSymbolAddress((void**)&A2,  g_A2);
    cudaGetSymbolAddress((void**)&O1,  g_O1);
    cudaGetSymbolAddress((void**)&O2,  g_O2);
    cudaGetSymbolAddress((void**)&G1,  g_G1);
    cudaGetSymbolAddress((void**)&G2,  g_G2);
    cudaGetSymbolAddress((void**)&U1,  g_U1);
    cudaGetSymbolAddress((void**)&U2,  g_U2);

    // 1) input rmsnorm
    rmsnorm_k<<<MVL, 256>>>(hs_vl, vl_ln1, X1, DVL);
    rmsnorm_k<<<MEX, 256>>>(hs_ex, ex_ln1, X2, DEX);

    // 2) QKV projections
    launch_gemm(X1, vl_wq, Qr1, MVL, HQ * DH,  DVL);
    launch_gemm(X1, vl_wk, Kr1, MVL, HKV * DH, DVL);
    launch_gemm(X1, vl_wv, Vr1, MVL, HKV * DH, DVL);
    launch_gemm(X2, ex_wq, Qr2, MEX, HQ * DH,  DEX);
    launch_gemm(X2, ex_wk, Kr2, MEX, HKV * DH, DEX);
    launch_gemm(X2, ex_wv, Vr2, MEX, HKV * DH, DEX);

    // 3) head rmsnorm + RoPE + scatter to [B,H,S,DH]
    qkv_post_k<<<dim3(SVL, HQ,  BB), 128>>>(Qr1, vl_qn, posids, Qc, HQ,  SVL, 0,   1, 1);
    qkv_post_k<<<dim3(SEX, HQ,  BB), 128>>>(Qr2, ex_qn, posids, Qc, HQ,  SEX, SVL, 1, 1);
    qkv_post_k<<<dim3(SVL, HKV, BB), 128>>>(Kr1, vl_kn, posids, Kc, HKV, SVL, 0,   1, 1);
    qkv_post_k<<<dim3(SEX, HKV, BB), 128>>>(Kr2, ex_kn, posids, Kc, HKV, SEX, SVL, 1, 1);
    qkv_post_k<<<dim3(SVL, HKV, BB), 128>>>(Vr1, nullptr, posids, Vc, HKV, SVL, 0,   0, 0);
    qkv_post_k<<<dim3(SEX, HKV, BB), 128>>>(Vr2, nullptr, posids, Vc, HKV, SEX, SVL, 0, 0);

    // 4) attention
    cudaFuncSetAttribute(attn_k, cudaFuncAttributeMaxDynamicSharedMemorySize, ATTN_SMEM);
    attn_k<<<dim3(SS / AQ, HQ, BB), 256, ATTN_SMEM>>>(Qc, Kc, Vc, mask, A1, A2);

    // 5) output projection + residual
    launch_gemm(A1, vl_wo, O1, MVL, DVL, HQ * DH, hs_vl);
    launch_gemm(A2, ex_wo, O2, MEX, DEX, HQ * DH, hs_ex);

    // 6) pre-MLP rmsnorm
    rmsnorm_k<<<MVL, 256>>>(O1, vl_ln2, X1, DVL);
    rmsnorm_k<<<MEX, 256>>>(O2, ex_ln2, X2, DEX);

    // 7) MLP up + gate
    launch_gemm(X1, vl_wg, G1, MVL, IVL, DVL);
    launch_gemm(X1, vl_wu, U1, MVL, IVL, DVL);
    launch_gemm(X2, ex_wg, G2, MEX, IEX, DEX);
    launch_gemm(X2, ex_wu, U2, MEX, IEX, DEX);
    silu_mul_k<<<(unsigned)(((size_t)MVL * IVL / 4 + 255) / 256), 256>>>(G1, U1, (size_t)MVL * IVL / 4);
    silu_mul_k<<<(unsigned)(((size_t)MEX * IEX / 4 + 255) / 256), 256>>>(G2, U2, (size_t)MEX * IEX / 4);

    // 8) down projection + residual -> outputs
    launch_gemm(G1, vl_wd, out_vl, MVL, DVL, IVL, O1);
    launch_gemm(G2, ex_wd, out_ex, MEX, DEX, IEX, O2);
}

// round 6
// speedup vs baseline: 1.8907x; 1.7227x over previous
#include <cuda_runtime.h>
#include <cuda_bf16.h>
#include <math.h>
#include <stdint.h>

// ---------------- problem constants ----------------
#define BB   4
#define SVL  1024
#define SEX  64
#define SS   1088
#define DVL  2048
#define DEX  1024
#define HQ   16
#define HKV  8
#define DH   128
#define IVL  6144
#define IEX  3072
#define MVL  (BB*SVL)      // 4096
#define MEX  (BB*SEX)      // 256
#define EPSV 1e-6f
#define ATT_SCALE 0.08838834764831845f
#define LOG2_THETA 22.253496664211536f

typedef __nv_bfloat16 bf16;

// ---------------- low-level helpers (base sm_103 target, no 'a' features) ----
__device__ __forceinline__ uint32_t smem_u32(const void* p) {
    uint32_t a;
    asm("{ .reg .u64 t; cvta.to.shared.u64 t, %1; cvt.u32.u64 %0, t; }" : "=r"(a) : "l"(p));
    return a;
}
__device__ __forceinline__ void ldsm4(uint32_t* r, uint32_t addr) {
    asm volatile("ldmatrix.sync.aligned.m8n8.x4.shared.b16 {%0,%1,%2,%3}, [%4];"
                 : "=r"(r[0]), "=r"(r[1]), "=r"(r[2]), "=r"(r[3]) : "r"(addr));
}
__device__ __forceinline__ void mma_bf16(float* c, const uint32_t* a, const uint32_t* b) {
    asm volatile("mma.sync.aligned.m16n8k16.row.col.f32.bf16.bf16.f32 "
                 "{%0,%1,%2,%3}, {%4,%5,%6,%7}, {%8,%9}, {%0,%1,%2,%3};"
                 : "+f"(c[0]), "+f"(c[1]), "+f"(c[2]), "+f"(c[3])
                 : "r"(a[0]), "r"(a[1]), "r"(a[2]), "r"(a[3]), "r"(b[0]), "r"(b[1]));
}
__device__ __forceinline__ void cpasync16(uint32_t dst, const void* src) {
    asm volatile("cp.async.cg.shared.global [%0], [%1], 16;" :: "r"(dst), "l"(src));
}
__device__ __forceinline__ void split2(float v, bf16& h, bf16& l) {
    h = __float2bfloat16(v);
    l = __float2bfloat16(v - __bfloat162float(h));
}

// ---------------- device scratch ----------------
__device__ bf16 g_vl_wqT[2][2048u*2048u];
__device__ bf16 g_vl_wkT[2][1024u*2048u];
__device__ bf16 g_vl_wvT[2][1024u*2048u];
__device__ bf16 g_vl_woT[2][2048u*2048u];
__device__ bf16 g_vl_wgT[2][6144u*2048u];
__device__ bf16 g_vl_wuT[2][6144u*2048u];
__device__ bf16 g_vl_wdT[2][2048u*6144u];
__device__ bf16 g_ex_wqT[2][2048u*1024u];
__device__ bf16 g_ex_wkT[2][1024u*1024u];
__device__ bf16 g_ex_wvT[2][1024u*1024u];
__device__ bf16 g_ex_woT[2][1024u*2048u];
__device__ bf16 g_ex_wgT[2][3072u*1024u];
__device__ bf16 g_ex_wuT[2][3072u*1024u];
__device__ bf16 g_ex_wdT[2][1024u*3072u];
__device__ bf16 g_X1s[2][(size_t)MVL*DVL];
__device__ bf16 g_X2s[2][(size_t)MEX*DEX];
__device__ float g_Qr1[(size_t)MVL*(HQ*DH)];
__device__ float g_Kr1[(size_t)MVL*(HKV*DH)];
__device__ float g_Vr1[(size_t)MVL*(HKV*DH)];
__device__ float g_Qr2[(size_t)MEX*(HQ*DH)];
__device__ float g_Kr2[(size_t)MEX*(HKV*DH)];
__device__ float g_Vr2[(size_t)MEX*(HKV*DH)];
__device__ float g_Q[(size_t)BB*HQ*SS*DH];
__device__ float g_K[(size_t)BB*HKV*SS*DH];
__device__ float g_V[(size_t)BB*HKV*SS*DH];
__device__ bf16 g_A1s[2][(size_t)MVL*(HQ*DH)];
__device__ bf16 g_A2s[2][(size_t)MEX*(HQ*DH)];
__device__ float g_O1[(size_t)MVL*DVL];
__device__ float g_O2[(size_t)MEX*DEX];
__device__ float g_G1[(size_t)MVL*IVL];
__device__ float g_U1[(size_t)MVL*IVL];
__device__ float g_G2[(size_t)MEX*IEX];
__device__ float g_U2[(size_t)MEX*IEX];
__device__ bf16 g_GU1s[2][(size_t)MVL*IVL];
__device__ bf16 g_GU2s[2][(size_t)MEX*IEX];

// ---------------- transpose + bf16-split: W[K][N] -> Th/Tl [N][K] ----------------
__global__ __launch_bounds__(256) void tsplit_k(const float* __restrict__ W,
                                                bf16* __restrict__ Th, bf16* __restrict__ Tl,
                                                int K, int N)
{
    __shared__ float t[32][33];
    const int n0 = blockIdx.x * 32, k0 = blockIdx.y * 32;
    const int tx = threadIdx.x, ty = threadIdx.y;
    #pragma unroll
    for (int j = 0; j < 4; j++)
        t[ty + 8 * j][tx] = W[(size_t)(k0 + ty + 8 * j) * N + n0 + tx];
    __syncthreads();
    #pragma unroll
    for (int j = 0; j < 4; j++) {
        const int n = n0 + ty + 8 * j;
        float v = t[tx][ty + 8 * j];
        bf16 h, l; split2(v, h, l);
        Th[(size_t)n * K + k0 + tx] = h;
        Tl[(size_t)n * K + k0 + tx] = l;
    }
}

// ---------------- rmsnorm -> bf16 hi/lo ----------------
__global__ __launch_bounds__(256) void rmsnorm_split_k(const float* __restrict__ x,
                                                       const float* __restrict__ w,
                                                       bf16* __restrict__ yh, bf16* __restrict__ yl,
                                                       int D)
{
    const int row = blockIdx.x;
    const float* xr = x + (size_t)row * D;
    float s = 0.f;
    for (int i = threadIdx.x; i < D; i += 256) { float v = xr[i]; s += v * v; }
    #pragma unroll
    for (int o = 16; o; o >>= 1) s += __shfl_xor_sync(0xffffffffu, s, o);
    __shared__ float ws[8];
    if ((threadIdx.x & 31) == 0) ws[threadIdx.x >> 5] = s;
    __syncthreads();
    float tot = 0.f;
    #pragma unroll
    for (int i = 0; i < 8; i++) tot += ws[i];
    const float r = rsqrtf(tot / (float)D + EPSV);
    for (int i = threadIdx.x; i < D; i += 256) {
        float v = xr[i] * r * w[i];
        bf16 h, l; split2(v, h, l);
        yh[(size_t)row * D + i] = h;
        yl[(size_t)row * D + i] = l;
    }
}

// ---------------- head rmsnorm + RoPE + scatter ----------------
__global__ __launch_bounds__(128) void qkv_post_k(const float* __restrict__ raw,
                                                  const float* __restrict__ w,
                                                  const int* __restrict__ pos_ids,
                                                  float* __restrict__ out,
                                                  int H, int sCount, int seqOff,
                                                  int doNorm, int doRope)
{
    __shared__ float sh[DH];
    __shared__ float ws[4];
    const int d = threadIdx.x;
    const int s = blockIdx.x, h = blockIdx.y, b = blockIdx.z;
    const int row = b * sCount + s;
    float v = raw[((size_t)row * H + h) * DH + d];
    if (doNorm) {
        float v2 = v * v;
        #pragma unroll
        for (int o = 16; o; o >>= 1) v2 += __shfl_xor_sync(0xffffffffu, v2, o);
        if ((d & 31) == 0) ws[d >> 5] = v2;
        __syncthreads();
        float tot = ws[0] + ws[1] + ws[2] + ws[3];
        v = v * rsqrtf(tot * (1.0f / DH) + EPSV) * w[d];
    }
    const int gs = seqOff + s;
    if (doRope) {
        sh[d] = v;
        __syncthreads();
        const float partner = (d < 64) ? -sh[d + 64] : sh[d - 64];
        const int pos = pos_ids[b * SS + gs];
        const float fr = (float)(d & 63) * (1.0f / 64.0f);
        const float invf = exp2f(-fr * LOG2_THETA);
        float sn, cs;
        sincosf((float)pos * invf, &sn, &cs);
        v = v * cs + partner * sn;
    }
    out[(((size_t)b * H + h) * SS + gs) * DH + d] = v;
}

// ---------------- bf16x3 warp-MMA GEMM: C[M,N] = A[M,K] @ Bt[N,K]^T (+R) ----------
// CTA 128x128, 8 warps (2x4), warp tile 64x32, KC=32, double-buffered cp.async.
#define KC 32
#define ROWB 80                          // padded row stride in bytes (40 bf16)
#define TILE_BYTES (128*ROWB)            // 10240
#define STAGE_BYTES (4*TILE_BYTES)       // 40960: Ah, Al, Bh, Bl
#define GEMM_SMEM (2*STAGE_BYTES)        // 81920

__device__ __forceinline__ void g_load_stage(uint32_t sb,
    const bf16* __restrict__ Ah, const bf16* __restrict__ Al,
    const bf16* __restrict__ Bh, const bf16* __restrict__ Bl,
    int bm, int bn, int K, int k0, int tid)
{
    #pragma unroll
    for (int h = 0; h < 2; h++) {
        const int row = (tid >> 2) + h * 64;
        const int cc = tid & 3;
        const uint32_t so = (uint32_t)row * ROWB + cc * 16;
        const size_t ga = (size_t)(bm + row) * K + k0 + cc * 8;
        const size_t gb = (size_t)(bn + row) * K + k0 + cc * 8;
        cpasync16(sb + so,                  Ah + ga);
        cpasync16(sb + TILE_BYTES + so,     Al + ga);
        cpasync16(sb + 2*TILE_BYTES + so,   Bh + gb);
        cpasync16(sb + 3*TILE_BYTES + so,   Bl + gb);
    }
    asm volatile("cp.async.commit_group;" ::: "memory");
}

__global__ __launch_bounds__(256, 1)
void mmagemm_k(const bf16* __restrict__ Ah, const bf16* __restrict__ Al,
               const bf16* __restrict__ Bh, const bf16* __restrict__ Bl,
               const float* __restrict__ R, float* __restrict__ C,
               int N, int K)
{
    extern __shared__ char smem[];
    const uint32_t smem_base = smem_u32(smem);
    const int tid = threadIdx.x;
    const int lane = tid & 31, warp = tid >> 5;
    const int wm = warp >> 2, wn = warp & 3;           // 2 x 4 warp grid
    const int bm = blockIdx.y * 128, bn = blockIdx.x * 128;

    float acc[16][4];
    #pragma unroll
    for (int i = 0; i < 16; i++)
        #pragma unroll
        for (int j = 0; j < 4; j++) acc[i][j] = 0.f;

    // ldmatrix lane offsets
    const int laneRA = (lane & 7) + ((lane >> 3) & 1) * 8;
    const int laneCA = (lane >> 4) * 8;
    const int jmB = lane >> 3;
    const int laneRB = (jmB >> 1) * 8 + (lane & 7);
    const int laneCB = (jmB & 1) * 8;

    const int nst = K / KC;
    g_load_stage(smem_base, Ah, Al, Bh, Bl, bm, bn, K, 0, tid);

    int buf = 0;
    for (int s = 0; s < nst; s++) {
        if (s + 1 < nst) {
            g_load_stage(smem_base + (buf ^ 1) * STAGE_BYTES, Ah, Al, Bh, Bl,
                         bm, bn, K, (s + 1) * KC, tid);
            asm volatile("cp.async.wait_group 1;" ::: "memory");
        } else {
            asm volatile("cp.async.wait_group 0;" ::: "memory");
        }
        __syncthreads();

        const uint32_t sb = smem_base + buf * STAGE_BYTES;
        #pragma unroll
        for (int kk = 0; kk < KC; kk += 16) {
            uint32_t ah[4][4], al[4][4], bh[2][4], bl[2][4];
            #pragma unroll
            for (int i = 0; i < 4; i++) {
                const uint32_t off = (uint32_t)(wm*64 + i*16 + laneRA) * ROWB
                                   + 2 * (laneCA + kk);
                ldsm4(ah[i], sb + off);
                ldsm4(al[i], sb + TILE_BYTES + off);
            }
            #pragma unroll
            for (int j = 0; j < 2; j++) {
                const uint32_t off = (uint32_t)(wn*32 + j*16 + laneRB) * ROWB
                                   + 2 * (laneCB + kk);
                ldsm4(bh[j], sb + 2*TILE_BYTES + off);
                ldsm4(bl[j], sb + 3*TILE_BYTES + off);
            }
            #pragma unroll
            for (int i = 0; i < 4; i++)
                #pragma unroll
                for (int j = 0; j < 4; j++) {
                    const uint32_t* bhp = &bh[j >> 1][(j & 1) * 2];
                    const uint32_t* blp = &bl[j >> 1][(j & 1) * 2];
                    mma_bf16(acc[i*4 + j], ah[i], bhp);
                    mma_bf16(acc[i*4 + j], ah[i], blp);
                    mma_bf16(acc[i*4 + j], al[i], bhp);
                }
        }
        __syncthreads();
        buf ^= 1;
    }

    // epilogue
    #pragma unroll
    for (int i = 0; i < 4; i++) {
        const int mrow = bm + wm*64 + i*16 + (lane >> 2);
        #pragma unroll
        for (int j = 0; j < 4; j++) {
            const int ncol = bn + wn*32 + j*8 + (lane & 3)*2;
            const float* a = acc[i*4 + j];
            const size_t i0 = (size_t)mrow * N + ncol;
            const size_t i1 = (size_t)(mrow + 8) * N + ncol;
            float2 v0 = make_float2(a[0], a[1]);
            float2 v1 = make_float2(a[2], a[3]);
            if (R) {
                float2 r0 = *(const float2*)(R + i0);
                float2 r1 = *(const float2*)(R + i1);
                v0.x += r0.x; v0.y += r0.y;
                v1.x += r1.x; v1.y += r1.y;
            }
            *(float2*)(C + i0) = v0;
            *(float2*)(C + i1) = v1;
        }
    }
}

// ---------------- silu(g)*u -> bf16 hi/lo ----------------
__global__ __launch_bounds__(256) void silu_split_k(const float* __restrict__ g,
                                                    const float* __restrict__ u,
                                                    bf16* __restrict__ oh, bf16* __restrict__ ol,
                                                    size_t n4)
{
    size_t i = (size_t)blockIdx.x * 256 + threadIdx.x;
    if (i >= n4) return;
    float4 gv = ((const float4*)g)[i];
    float4 uv = ((const float4*)u)[i];
    float vv[4];
    vv[0] = gv.x / (1.f + __expf(-gv.x)) * uv.x;
    vv[1] = gv.y / (1.f + __expf(-gv.y)) * uv.y;
    vv[2] = gv.z / (1.f + __expf(-gv.z)) * uv.z;
    vv[3] = gv.w / (1.f + __expf(-gv.w)) * uv.w;
    #pragma unroll
    for (int j = 0; j < 4; j++) {
        bf16 h, l; split2(vv[j], h, l);
        oh[i * 4 + j] = h;
        ol[i * 4 + j] = l;
    }
}

// ---------------- flash attention (fp32), outputs bf16 hi/lo ----------------
#define AQ 64
#define AK 32
#define QPAD 132
#define SPAD 33
#define ATTN_SMEM ((AQ*QPAD + AK*QPAD + AK*QPAD + AQ*SPAD + 3*AQ) * 4)

__global__ __launch_bounds__(256) void attn_k(const float* __restrict__ Q,
                                              const float* __restrict__ Kg,
                                              const float* __restrict__ Vg,
                                              const float* __restrict__ mask,
                                              bf16* __restrict__ a1h, bf16* __restrict__ a1l,
                                              bf16* __restrict__ a2h, bf16* __restrict__ a2l)
{
    extern __shared__ float sm[];
    float* Qs   = sm;
    float* Ks   = Qs + AQ * QPAD;
    float* Vs   = Ks + AK * QPAD;
    float* Scr  = Vs + AK * QPAD;
    float* mrow = Scr + AQ * SPAD;
    float* lrow = mrow + AQ;
    float* crow = lrow + AQ;

    const int tid = threadIdx.x;
    const int b = blockIdx.z, h = blockIdx.y;
    const int q0 = blockIdx.x * AQ;
    const int kvh = h >> 1;
    const float* Qb = Q  + ((size_t)(b * HQ  + h)   * SS + q0) * DH;
    const float* Kb = Kg + ((size_t)(b * HKV + kvh) * SS) * DH;
    const float* Vb = Vg + ((size_t)(b * HKV + kvh) * SS) * DH;

    for (int i = tid * 4; i < AQ * DH; i += 1024) {
        int r = i >> 7, c = i & 127;
        *(float4*)&Qs[r * QPAD + c] = *(const float4*)&Qb[i];
    }
    if (tid < AQ) { mrow[tid] = -1e30f; lrow[tid] = 0.f; }
    const int ty = tid >> 4, tx = tid & 15;
    float acc[4][8];
    #pragma unroll
    for (int m = 0; m < 4; m++)
        #pragma unroll
        for (int d = 0; d < 8; d++) acc[m][d] = 0.f;
    __syncthreads();

    for (int k0 = 0; k0 < SS; k0 += AK) {
        for (int i = tid * 4; i < AK * DH; i += 1024) {
            int r = i >> 7, c = i & 127;
            *(float4*)&Ks[r * QPAD + c] = *(const float4*)&Kb[(size_t)k0 * DH + i];
            *(float4*)&Vs[r * QPAD + c] = *(const float4*)&Vb[(size_t)k0 * DH + i];
        }
        __syncthreads();

        float sacc[4][2] = {};
        #pragma unroll 8
        for (int kk = 0; kk < DH; kk += 4) {
            float4 kv0 = *(const float4*)&Ks[(tx * 2 + 0) * QPAD + kk];
            float4 kv1 = *(const float4*)&Ks[(tx * 2 + 1) * QPAD + kk];
            #pragma unroll
            for (int m = 0; m < 4; m++) {
                float4 qv = *(const float4*)&Qs[(ty * 4 + m) * QPAD + kk];
                sacc[m][0] += qv.x*kv0.x + qv.y*kv0.y + qv.z*kv0.z + qv.w*kv0.w;
                sacc[m][1] += qv.x*kv1.x + qv.y*kv1.y + qv.z*kv1.z + qv.w*kv1.w;
            }
        }
        #pragma unroll
        for (int m = 0; m < 4; m++)
            #pragma unroll
            for (int n = 0; n < 2; n++) {
                const int qr = q0 + ty * 4 + m;
                const int kc = k0 + tx * 2 + n;
                Scr[(ty * 4 + m) * SPAD + (tx * 2 + n)] =
                    sacc[m][n] * ATT_SCALE + mask[((size_t)b * SS + qr) * SS + kc];
            }
        __syncthreads();

        if (tid < AQ) {
            float mo = mrow[tid], mx = mo;
            #pragma unroll 8
            for (int c = 0; c < AK; c++) mx = fmaxf(mx, Scr[tid * SPAD + c]);
            float corr = __expf(mo - mx);
            float l = lrow[tid] * corr, ps = 0.f;
            #pragma unroll 8
            for (int c = 0; c < AK; c++) {
                float p = __expf(Scr[tid * SPAD + c] - mx);
                Scr[tid * SPAD + c] = p;
                ps += p;
            }
            mrow[tid] = mx; lrow[tid] = l + ps; crow[tid] = corr;
        }
        __syncthreads();

        float cr[4];
        #pragma unroll
        for (int m = 0; m < 4; m++) cr[m] = crow[ty * 4 + m];
        #pragma unroll
        for (int m = 0; m < 4; m++)
            #pragma unroll
            for (int d = 0; d < 8; d++) acc[m][d] *= cr[m];
        #pragma unroll 4
        for (int c = 0; c < AK; c++) {
            float4 v0 = *(const float4*)&Vs[c * QPAD + tx * 8];
            float4 v1 = *(const float4*)&Vs[c * QPAD + tx * 8 + 4];
            #pragma unroll
            for (int m = 0; m < 4; m++) {
                float p = Scr[(ty * 4 + m) * SPAD + c];
                acc[m][0] += p * v0.x; acc[m][1] += p * v0.y;
                acc[m][2] += p * v0.z; acc[m][3] += p * v0.w;
                acc[m][4] += p * v1.x; acc[m][5] += p * v1.y;
                acc[m][6] += p * v1.z; acc[m][7] += p * v1.w;
            }
        }
        __syncthreads();
    }

    #pragma unroll
    for (int m = 0; m < 4; m++) {
        const int qr = q0 + ty * 4 + m;
        const float li = 1.f / lrow[ty * 4 + m];
        size_t idx;
        bf16 *oh, *ol;
        if (qr < SVL) {
            idx = ((size_t)(b * SVL + qr)) * (HQ * DH) + h * DH + tx * 8;
            oh = a1h; ol = a1l;
        } else {
            idx = ((size_t)(b * SEX + (qr - SVL))) * (HQ * DH) + h * DH + tx * 8;
            oh = a2h; ol = a2l;
        }
        #pragma unroll
        for (int d = 0; d < 8; d++) {
            bf16 hh, ll; split2(acc[m][d] * li, hh, ll);
            oh[idx + d] = hh;
            ol[idx + d] = ll;
        }
    }
}

// ---------------- launch ----------------
extern "C" void kernel_launch(void* const* d_in, const int* in_sizes, int n_in,
                              void* d_out, int out_size)
{
    (void)in_sizes; (void)n_in; (void)out_size;
    const float* hs_vl  = (const float*)d_in[0];
    const float* hs_ex  = (const float*)d_in[1];
    const int*   posids = (const int*)  d_in[2];
    const float* mask   = (const float*)d_in[3];
    const float* vl_ln1 = (const float*)d_in[4];
    const float* vl_wq  = (const float*)d_in[5];
    const float* vl_wk  = (const float*)d_in[6];
    const float* vl_wv  = (const float*)d_in[7];
    const float* vl_qn  = (const float*)d_in[8];
    const float* vl_kn  = (const float*)d_in[9];
    const float* vl_wo  = (const float*)d_in[10];
    const float* vl_ln2 = (const float*)d_in[11];
    const float* vl_wg  = (const float*)d_in[12];
    const float* vl_wu  = (const float*)d_in[13];
    const float* vl_wd  = (const float*)d_in[14];
    const float* ex_ln1 = (const float*)d_in[15];
    const float* ex_wq  = (const float*)d_in[16];
    const float* ex_wk  = (const float*)d_in[17];
    const float* ex_wv  = (const float*)d_in[18];
    const float* ex_qn  = (const float*)d_in[19];
    const float* ex_kn  = (const float*)d_in[20];
    const float* ex_wo  = (const float*)d_in[21];
    const float* ex_ln2 = (const float*)d_in[22];
    const float* ex_wg  = (const float*)d_in[23];
    const float* ex_wu  = (const float*)d_in[24];
    const float* ex_wd  = (const float*)d_in[25];

    float* out_vl = (float*)d_out;
    float* out_ex = out_vl + (size_t)MVL * DVL;

#define SYM(T, p, s) T* p; cudaGetSymbolAddress((void**)&p, s)
    SYM(bf16, vl_wqT, g_vl_wqT); SYM(bf16, vl_wkT, g_vl_wkT); SYM(bf16, vl_wvT, g_vl_wvT);
    SYM(bf16, vl_woT, g_vl_woT); SYM(bf16, vl_wgT, g_vl_wgT); SYM(bf16, vl_wuT, g_vl_wuT);
    SYM(bf16, vl_wdT, g_vl_wdT);
    SYM(bf16, ex_wqT, g_ex_wqT); SYM(bf16, ex_wkT, g_ex_wkT); SYM(bf16, ex_wvT, g_ex_wvT);
    SYM(bf16, ex_woT, g_ex_woT); SYM(bf16, ex_wgT, g_ex_wgT); SYM(bf16, ex_wuT, g_ex_wuT);
    SYM(bf16, ex_wdT, g_ex_wdT);
    SYM(bf16, X1s, g_X1s); SYM(bf16, X2s, g_X2s);
    SYM(float, Qr1, g_Qr1); SYM(float, Kr1, g_Kr1); SYM(float, Vr1, g_Vr1);
    SYM(float, Qr2, g_Qr2); SYM(float, Kr2, g_Kr2); SYM(float, Vr2, g_Vr2);
    SYM(float, Qc, g_Q); SYM(float, Kc, g_K); SYM(float, Vc, g_V);
    SYM(bf16, A1s, g_A1s); SYM(bf16, A2s, g_A2s);
    SYM(float, O1, g_O1); SYM(float, O2, g_O2);
    SYM(float, G1, g_G1); SYM(float, U1, g_U1);
    SYM(float, G2, g_G2); SYM(float, U2, g_U2);
    SYM(bf16, GU1s, g_GU1s); SYM(bf16, GU2s, g_GU2s);
#undef SYM

    cudaFuncSetAttribute(mmagemm_k, cudaFuncAttributeMaxDynamicSharedMemorySize, GEMM_SMEM);
    cudaFuncSetAttribute(attn_k, cudaFuncAttributeMaxDynamicSharedMemorySize, ATTN_SMEM);

    // --- 0) weight transpose + split ---
#define TS(W, T, KK, NN) tsplit_k<<<dim3((NN)/32, (KK)/32), dim3(32, 8)>>>(W, (T), (T) + (size_t)(KK)*(NN), KK, NN)
    TS(vl_wq, vl_wqT, 2048, 2048);
    TS(vl_wk, vl_wkT, 2048, 1024);
    TS(vl_wv, vl_wvT, 2048, 1024);
    TS(vl_wo, vl_woT, 2048, 2048);
    TS(vl_wg, vl_wgT, 2048, 6144);
    TS(vl_wu, vl_wuT, 2048, 6144);
    TS(vl_wd, vl_wdT, 6144, 2048);
    TS(ex_wq, ex_wqT, 1024, 2048);
    TS(ex_wk, ex_wkT, 1024, 1024);
    TS(ex_wv, ex_wvT, 1024, 1024);
    TS(ex_wo, ex_woT, 2048, 1024);
    TS(ex_wg, ex_wgT, 1024, 3072);
    TS(ex_wu, ex_wuT, 1024, 3072);
    TS(ex_wd, ex_wdT, 3072, 1024);
#undef TS

#define TG(AH, AL, BT, BN, BK, Rr, Cc, M, N, K) \
    mmagemm_k<<<dim3((N)/128, (M)/128), 256, GEMM_SMEM>>>( \
        AH, AL, BT, (BT) + (size_t)(BN)*(BK), Rr, Cc, N, K)

    const size_t NX1 = (size_t)MVL * DVL, NX2 = (size_t)MEX * DEX;
    const size_t NA1 = (size_t)MVL * (HQ * DH), NA2 = (size_t)MEX * (HQ * DH);
    const size_t NG1 = (size_t)MVL * IVL, NG2 = (size_t)MEX * IEX;

    // --- 1) input rmsnorm -> X splits ---
    rmsnorm_split_k<<<MVL, 256>>>(hs_vl, vl_ln1, X1s, X1s + NX1, DVL);
    rmsnorm_split_k<<<MEX, 256>>>(hs_ex, ex_ln1, X2s, X2s + NX2, DEX);

    // --- 2) QKV projections ---
    TG(X1s, X1s + NX1, vl_wqT, 2048, 2048, nullptr, Qr1, MVL, 2048, 2048);
    TG(X1s, X1s + NX1, vl_wkT, 1024, 2048, nullptr, Kr1, MVL, 1024, 2048);
    TG(X1s, X1s + NX1, vl_wvT, 1024, 2048, nullptr, Vr1, MVL, 1024, 2048);
    TG(X2s, X2s + NX2, ex_wqT, 2048, 1024, nullptr, Qr2, MEX, 2048, 1024);
    TG(X2s, X2s + NX2, ex_wkT, 1024, 1024, nullptr, Kr2, MEX, 1024, 1024);
    TG(X2s, X2s + NX2, ex_wvT, 1024, 1024, nullptr, Vr2, MEX, 1024, 1024);

    // --- 3) head rmsnorm + RoPE + scatter ---
    qkv_post_k<<<dim3(SVL, HQ,  BB), 128>>>(Qr1, vl_qn, posids, Qc, HQ,  SVL, 0,   1, 1);
    qkv_post_k<<<dim3(SEX, HQ,  BB), 128>>>(Qr2, ex_qn, posids, Qc, HQ,  SEX, SVL, 1, 1);
    qkv_post_k<<<dim3(SVL, HKV, BB), 128>>>(Kr1, vl_kn, posids, Kc, HKV, SVL, 0,   1, 1);
    qkv_post_k<<<dim3(SEX, HKV, BB), 128>>>(Kr2, ex_kn, posids, Kc, HKV, SEX, SVL, 1, 1);
    qkv_post_k<<<dim3(SVL, HKV, BB), 128>>>(Vr1, nullptr, posids, Vc, HKV, SVL, 0,   0, 0);
    qkv_post_k<<<dim3(SEX, HKV, BB), 128>>>(Vr2, nullptr, posids, Vc, HKV, SEX, SVL, 0, 0);

    // --- 4) attention (writes A splits) ---
    attn_k<<<dim3(SS / AQ, HQ, BB), 256, ATTN_SMEM>>>(Qc, Kc, Vc, mask,
                                                      A1s, A1s + NA1, A2s, A2s + NA2);

    // --- 5) output projection + residual ---
    TG(A1s, A1s + NA1, vl_woT, 2048, 2048, hs_vl, O1, MVL, 2048, 2048);
    TG(A2s, A2s + NA2, ex_woT, 1024, 2048, hs_ex, O2, MEX, 1024, 2048);

    // --- 6) pre-MLP rmsnorm -> X splits ---
    rmsnorm_split_k<<<MVL, 256>>>(O1, vl_ln2, X1s, X1s + NX1, DVL);
    rmsnorm_split_k<<<MEX, 256>>>(O2, ex_ln2, X2s, X2s + NX2, DEX);

    // --- 7) MLP gate/up GEMMs + silu*mul -> GU splits ---
    TG(X1s, X1s + NX1, vl_wgT, 6144, 2048, nullptr, G1, MVL, 6144, 2048);
    TG(X1s, X1s + NX1, vl_wuT, 6144, 2048, nullptr, U1, MVL, 6144, 2048);
    TG(X2s, X2s + NX2, ex_wgT, 3072, 1024, nullptr, G2, MEX, 3072, 1024);
    TG(X2s, X2s + NX2, ex_wuT, 3072, 1024, nullptr, U2, MEX, 3072, 1024);
    silu_split_k<<<(unsigned)((NG1 / 4 + 255) / 256), 256>>>(G1, U1, GU1s, GU1s + NG1, NG1 / 4);
    silu_split_k<<<(unsigned)((NG2 / 4 + 255) / 256), 256>>>(G2, U2, GU2s, GU2s + NG2, NG2 / 4);

    // --- 8) down projection + residual -> outputs ---
    TG(GU1s, GU1s + NG1, vl_wdT, 2048, 6144, O1, out_vl, MVL, 2048, 6144);
    TG(GU2s, GU2s + NG2, ex_wdT, 1024, 3072, O2, out_ex, MEX, 1024, 3072);
#undef TG
}